// round 15
// baseline (speedup 1.0000x reference)
#include <cuda_runtime.h>
#include <cuda_fp16.h>
#include <stdint.h>

constexpr int Bc = 4, Hc = 16, Pp = 1024, Dd = 128;
constexpr int NELEM = Bc * Hc * Pp * Dd;   // 8388608
constexpr int BM = 32;       // query rows per item
constexpr int TN = 128;      // keys per tile
constexpr int NT = Pp / TN;  // 8 tiles
constexpr int NITEMS = 2048; // 32 mtiles x 64 bh
constexpr int NCTAS = 152;   // GB300 SM count (1 CTA/SM, persistent)

// ---- device scratch: silu'd q, k as fp16 ----
__device__ __half g_qh[NELEM], g_kh[NELEM];

// ---- smem layout (bytes) ----
constexpr int OFF_Q   = 0;        // 32 rows x 256B (swizzled) = 8192
constexpr int OFF_K   = 8192;     // 16 warps x 4 slots x 2KB = 131072
constexpr int OFF_SC  = 139264;   // 32 rows x 2048B fp16 scores = 65536
constexpr int OFF_RS  = 204800;   // 32 rows x 16 warps x 4B = 2048 (row-major)
constexpr int OFF_INV = 206848;   // 32 x 4B
constexpr int SMEM2   = 206976;

// =================== helpers ===================
__device__ __forceinline__ uint32_t smem_u32(const void* p) {
    uint32_t a;
    asm("{ .reg .u64 t; cvta.to.shared.u64 t, %1; cvt.u32.u64 %0, t; }" : "=r"(a) : "l"(p));
    return a;
}
__device__ __forceinline__ void cpa16(uint32_t dst, const void* src) {
    asm volatile("cp.async.cg.shared.global [%0], [%1], 16;" :: "r"(dst), "l"(src));
}
__device__ __forceinline__ void cpa_commit() { asm volatile("cp.async.commit_group;" ::: "memory"); }
template<int N>
__device__ __forceinline__ void cpa_wait() { asm volatile("cp.async.wait_group %0;" :: "n"(N) : "memory"); }

__device__ __forceinline__ void ldsm4(uint32_t* r, uint32_t addr) {
    asm volatile("ldmatrix.sync.aligned.m8n8.x4.shared.b16 {%0,%1,%2,%3}, [%4];"
                 : "=r"(r[0]), "=r"(r[1]), "=r"(r[2]), "=r"(r[3]) : "r"(addr));
}
__device__ __forceinline__ void mma16816(float* d, const uint32_t* a, uint32_t b0, uint32_t b1) {
    asm volatile(
        "mma.sync.aligned.m16n8k16.row.col.f32.f16.f16.f32 "
        "{%0,%1,%2,%3}, {%4,%5,%6,%7}, {%8,%9}, {%0,%1,%2,%3};"
        : "+f"(d[0]), "+f"(d[1]), "+f"(d[2]), "+f"(d[3])
        : "r"(a[0]), "r"(a[1]), "r"(a[2]), "r"(a[3]), "r"(b0), "r"(b1));
}
__device__ __forceinline__ void sts32(uint32_t addr, uint32_t v) {
    asm volatile("st.shared.u32 [%0], %1;" :: "r"(addr), "r"(v) : "memory");
}
__device__ __forceinline__ void lds64(uint32_t& a, uint32_t& b, uint32_t addr) {
    asm volatile("ld.shared.v2.u32 {%0,%1}, [%2];" : "=r"(a), "=r"(b) : "r"(addr));
}
__device__ __forceinline__ float silu_f(float x) {
    return x * (1.0f / (1.0f + __expf(-x)));
}
__device__ __forceinline__ uint32_t pack_h2(__half a, __half b) {
    __half2 t(a, b);
    return *reinterpret_cast<uint32_t*>(&t);
}
__device__ __forceinline__ uint32_t f2h2(float a, float b) {
    __half2 t = __floats2half2_rn(a, b);
    return *reinterpret_cast<uint32_t*>(&t);
}
__device__ __forceinline__ uint4 silu_pack8(float4 a, float4 b) {
    uint4 o;
    o.x = pack_h2(__float2half(silu_f(a.x)), __float2half(silu_f(a.y)));
    o.y = pack_h2(__float2half(silu_f(a.z)), __float2half(silu_f(a.w)));
    o.z = pack_h2(__float2half(silu_f(b.x)), __float2half(silu_f(b.y)));
    o.w = pack_h2(__float2half(silu_f(b.z)), __float2half(silu_f(b.w)));
    return o;
}

// =================== Pass 1: silu -> fp16 (16 elems/tensor/thread, streaming) ===================
__global__ void __launch_bounds__(256)
silu_split_kernel(const float* __restrict__ q, const float* __restrict__ k)
{
    int j = blockIdx.x * 256 + threadIdx.x;          // 16-elem group index
    const float4* q4 = (const float4*)q + (size_t)j * 4;
    const float4* k4 = (const float4*)k + (size_t)j * 4;

    // 8 independent streaming loads in flight
    float4 qa = __ldcs(q4 + 0), qb = __ldcs(q4 + 1), qc = __ldcs(q4 + 2), qd = __ldcs(q4 + 3);
    float4 ka = __ldcs(k4 + 0), kb = __ldcs(k4 + 1), kc = __ldcs(k4 + 2), kd = __ldcs(k4 + 3);

    uint4* qo = (uint4*)g_qh + (size_t)j * 2;
    uint4* ko = (uint4*)g_kh + (size_t)j * 2;
    __stcs(qo + 0, silu_pack8(qa, qb));
    __stcs(qo + 1, silu_pack8(qc, qd));
    __stcs(ko + 0, silu_pack8(ka, kb));
    __stcs(ko + 1, silu_pack8(kc, kd));
}

// =================== Pass 2: persistent HMMA GEMM + fused softmax (R12 body) ===================
// 152 persistent CTAs x 512 threads (16 warp-private pipelines). Item = 32 query
// rows x one (b,h). B fragments for two ks-steps fetched in ONE ldsm.x4 via
// bsel = (lane>>3)&3. Next item's Q + K prologue prefetched during epilogue.
__global__ void __launch_bounds__(512, 1)
attn_mma_kernel(const float* __restrict__ scale_p, float* __restrict__ out)
{
    extern __shared__ char smem[];
    const uint32_t sb = smem_u32(smem);
    const int tid = threadIdx.x, lane = tid & 31, w = tid >> 5;
    const float sc = scale_p[0];

    const uint32_t myring = sb + OFF_K + (uint32_t)w * 8192;
    const uint32_t scb = sb + OFF_SC;
    float* rs  = (float*)(smem + OFF_RS);    // [32 rows][16 warps]
    float* inv = (float*)(smem + OFF_INV);

    // Q chunk owned by this thread (row = tid>>4, c = tid&15)
    const int qrow = tid >> 4, qc = tid & 15;
    const uint32_t qoff = sb + OFF_Q + qrow * 256 + (((qc ^ (qrow & 7)) & 15) << 4);

    auto pfQ = [&](int item) {
        int bh = item >> 5, mtile = item & 31;
        const char* src = (const char*)g_qh +
            (((size_t)(bh * Pp + mtile * BM) + qrow) * 256 + qc * 16);
        cpa16(qoff, src);
        cpa_commit();
    };
    auto pfK = [&](int item, int t) {
        int bh = item >> 5;
        uint32_t dst = myring + (uint32_t)(t & 3) * 2048;
        const char* src = (const char*)g_kh +
            ((size_t)(bh * Pp + t * TN + w * 8)) * 256;
        #pragma unroll
        for (int i = 0; i < 4; ++i) {
            int idx = lane + (i << 5);
            int key = idx >> 4, c = idx & 15;
            uint32_t off = (uint32_t)(key * 256) + (((c ^ (key & 7)) & 15) << 4);
            cpa16(dst + off, src + key * 256 + c * 16);
        }
        cpa_commit();
    };

    // fragment addressing constants
    const int lm = lane >> 3, lr = lane & 7;
    const int brow = lane & 7;
    const int bsel = (lane >> 3) & 3;     // ldsm.x4 fetches chunks of ks AND ks+1
    const uint32_t browoff = (uint32_t)brow * 256;
    const int r0 = lane >> 2;
    const uint32_t rx = (uint32_t)((r0 & 7) << 4);
    const uint32_t kcolbyte = (uint32_t)(w * 16 + 4 * (lane & 3));

    int item = blockIdx.x;
    if (item < NITEMS) {
        pfQ(item);
        #pragma unroll
        for (int t = 0; t < 4; ++t) pfK(item, t);
    }

    while (item < NITEMS) {
        const int next = item + NCTAS;
        const int bh = item >> 5, mtile = item & 31;

        cpa_wait<4>();      // Q arrived (K0..K3 may be pending)
        __syncthreads();    // Q visible CTA-wide; score buffer free for reuse

        // ---- hoist Q fragments (2 row-groups x 8 ks) ----
        uint32_t aq[2][8][4];
        #pragma unroll
        for (int rg = 0; rg < 2; ++rg) {
            int arow = rg * 16 + ((lm & 1) << 3) + lr;
            uint32_t arow256 = (uint32_t)arow * 256;
            int ax7 = arow & 7, amc = lm >> 1;
            #pragma unroll
            for (int ks = 0; ks < 8; ++ks) {
                uint32_t ac = (uint32_t)((((2 * ks + amc) ^ ax7) & 15) << 4);
                ldsm4(aq[rg][ks], sb + OFF_Q + arow256 + ac);
            }
        }

        float s[4] = {0.f, 0.f, 0.f, 0.f};

        #pragma unroll
        for (int t = 0; t < NT; ++t) {
            if (t <= 4) cpa_wait<3>();
            else if (t == 5) cpa_wait<2>();
            else if (t == 6) cpa_wait<1>();
            else cpa_wait<0>();

            const uint32_t Kb = myring + (uint32_t)(t & 3) * 2048;
            float acc0[4] = {0.f, 0.f, 0.f, 0.f};
            float acc1[4] = {0.f, 0.f, 0.f, 0.f};

            #pragma unroll
            for (int ks = 0; ks < 8; ks += 2) {
                uint32_t b4[4];   // mats {0,1}: ks lo/hi; {2,3}: ks+1 lo/hi
                uint32_t bc = (uint32_t)((((2 * ks + bsel) ^ brow) & 15) << 4);
                ldsm4(b4, Kb + browoff + bc);
                mma16816(acc0, aq[0][ks],     b4[0], b4[1]);
                mma16816(acc1, aq[1][ks],     b4[0], b4[1]);
                mma16816(acc0, aq[0][ks + 1], b4[2], b4[3]);
                mma16816(acc1, aq[1][ks + 1], b4[2], b4[3]);
            }

            if (t + 4 < NT) pfK(item, t + 4);   // refill slot t&3

            // exp + fp32 sums + fp16 pack + swizzled STS
            uint32_t kb = (uint32_t)t * 256 + kcolbyte;
            float e0, e1;
            e0 = __expf(sc * acc0[0]); e1 = __expf(sc * acc0[1]); s[0] += e0 + e1;
            sts32(scb + (uint32_t)r0 * 2048        + (kb ^ rx), f2h2(e0, e1));
            e0 = __expf(sc * acc0[2]); e1 = __expf(sc * acc0[3]); s[1] += e0 + e1;
            sts32(scb + (uint32_t)(r0 + 8) * 2048  + (kb ^ rx), f2h2(e0, e1));
            e0 = __expf(sc * acc1[0]); e1 = __expf(sc * acc1[1]); s[2] += e0 + e1;
            sts32(scb + (uint32_t)(r0 + 16) * 2048 + (kb ^ rx), f2h2(e0, e1));
            e0 = __expf(sc * acc1[2]); e1 = __expf(sc * acc1[3]); s[3] += e0 + e1;
            sts32(scb + (uint32_t)(r0 + 24) * 2048 + (kb ^ rx), f2h2(e0, e1));
        }

        // ---- prefetch next item's Q + K prologue (overlaps epilogue) ----
        if (next < NITEMS) {
            pfQ(next);
            #pragma unroll
            for (int t = 0; t < 4; ++t) pfK(next, t);
        }

        // ---- row sums: reduce over key-lanes, then over warps ----
        #pragma unroll
        for (int o = 1; o < 4; o <<= 1) {
            s[0] += __shfl_xor_sync(0xFFFFFFFFu, s[0], o);
            s[1] += __shfl_xor_sync(0xFFFFFFFFu, s[1], o);
            s[2] += __shfl_xor_sync(0xFFFFFFFFu, s[2], o);
            s[3] += __shfl_xor_sync(0xFFFFFFFFu, s[3], o);
        }
        if ((lane & 3) == 0) {
            rs[(r0)      * 16 + w] = s[0];
            rs[(r0 + 8)  * 16 + w] = s[1];
            rs[(r0 + 16) * 16 + w] = s[2];
            rs[(r0 + 24) * 16 + w] = s[3];
        }
        __syncthreads();   // publishes all score STS + rs
        if (tid < 256) {
            int row = tid >> 3, pi = tid & 7;
            float2 v = ((const float2*)rs)[row * 8 + pi];
            float tot = v.x + v.y;
            tot += __shfl_xor_sync(0xFFFFFFFFu, tot, 1);
            tot += __shfl_xor_sync(0xFFFFFFFFu, tot, 2);
            tot += __shfl_xor_sync(0xFFFFFFFFu, tot, 4);
            if (pi == 0) inv[row] = 1.0f / tot;
        }
        __syncthreads();

        // ---- coalesced normalize + store ----
        const int row = tid >> 4, cc = tid & 15;
        const float iv = inv[row];
        float* orow = out + ((size_t)bh * Pp + mtile * BM + row) * Pp;
        const uint32_t rbase = scb + (uint32_t)row * 2048;
        const uint32_t rxr = (uint32_t)((row & 7) << 4);
        #pragma unroll
        for (int p = 0; p < 16; ++p) {
            int key = cc * 4 + p * 64;
            uint32_t a, b;
            lds64(a, b, rbase + (((uint32_t)(key * 2)) ^ rxr));
            __half2 ha = *reinterpret_cast<__half2*>(&a);
            __half2 hb = *reinterpret_cast<__half2*>(&b);
            float2 fa = __half22float2(ha);
            float2 fb = __half22float2(hb);
            float4 v = make_float4(fa.x * iv, fa.y * iv, fb.x * iv, fb.y * iv);
            *(float4*)(orow + key) = v;
        }

        item = next;
    }
}

// =================== launch ===================
extern "C" void kernel_launch(void* const* d_in, const int* in_sizes, int n_in,
                              void* d_out, int out_size)
{
    const float* q     = (const float*)d_in[0];
    const float* k     = (const float*)d_in[1];
    const float* scale = (const float*)d_in[2];
    float* out = (float*)d_out;

    silu_split_kernel<<<NELEM / 16 / 256, 256>>>(q, k);

    cudaFuncSetAttribute(attn_mma_kernel,
                         cudaFuncAttributeMaxDynamicSharedMemorySize, SMEM2);
    attn_mma_kernel<<<NCTAS, 512, SMEM2>>>(scale, out);
}

// round 16
// speedup vs baseline: 1.0211x; 1.0211x over previous
#include <cuda_runtime.h>
#include <cuda_fp16.h>
#include <stdint.h>

constexpr int Bc = 4, Hc = 16, Pp = 1024, Dd = 128;
constexpr int NELEM = Bc * Hc * Pp * Dd;   // 8388608
constexpr int BM = 32;       // query rows per item
constexpr int TN = 128;      // keys per tile
constexpr int NT = Pp / TN;  // 8 tiles
constexpr int NITEMS = 2048; // 32 mtiles x 64 bh
constexpr int NCTAS = 152;   // GB300 SM count (1 CTA/SM, persistent)

// ---- device scratch: silu'd q, k as fp16 ----
__device__ __half g_qh[NELEM], g_kh[NELEM];

// ---- smem layout (bytes) ----
constexpr int OFF_Q   = 0;        // 2 bufs x 32 rows x 256B (swizzled) = 16384
constexpr int OFF_K   = 16384;    // 16 warps x 4 slots x 2KB = 131072
constexpr int OFF_SC  = 147456;   // 32 rows x 2048B fp16 scores = 65536
constexpr int OFF_RS  = 212992;   // 32 rows x 16 warps x 4B = 2048
constexpr int SMEM2   = 215040;

// =================== helpers ===================
__device__ __forceinline__ uint32_t smem_u32(const void* p) {
    uint32_t a;
    asm("{ .reg .u64 t; cvta.to.shared.u64 t, %1; cvt.u32.u64 %0, t; }" : "=r"(a) : "l"(p));
    return a;
}
__device__ __forceinline__ void cpa16(uint32_t dst, const void* src) {
    asm volatile("cp.async.cg.shared.global [%0], [%1], 16;" :: "r"(dst), "l"(src));
}
__device__ __forceinline__ void cpa_commit() { asm volatile("cp.async.commit_group;" ::: "memory"); }
template<int N>
__device__ __forceinline__ void cpa_wait() { asm volatile("cp.async.wait_group %0;" :: "n"(N) : "memory"); }

__device__ __forceinline__ void ldsm4(uint32_t* r, uint32_t addr) {
    asm volatile("ldmatrix.sync.aligned.m8n8.x4.shared.b16 {%0,%1,%2,%3}, [%4];"
                 : "=r"(r[0]), "=r"(r[1]), "=r"(r[2]), "=r"(r[3]) : "r"(addr));
}
__device__ __forceinline__ void mma16816(float* d, const uint32_t* a, uint32_t b0, uint32_t b1) {
    asm volatile(
        "mma.sync.aligned.m16n8k16.row.col.f32.f16.f16.f32 "
        "{%0,%1,%2,%3}, {%4,%5,%6,%7}, {%8,%9}, {%0,%1,%2,%3};"
        : "+f"(d[0]), "+f"(d[1]), "+f"(d[2]), "+f"(d[3])
        : "r"(a[0]), "r"(a[1]), "r"(a[2]), "r"(a[3]), "r"(b0), "r"(b1));
}
__device__ __forceinline__ void sts32(uint32_t addr, uint32_t v) {
    asm volatile("st.shared.u32 [%0], %1;" :: "r"(addr), "r"(v) : "memory");
}
__device__ __forceinline__ void lds64(uint32_t& a, uint32_t& b, uint32_t addr) {
    asm volatile("ld.shared.v2.u32 {%0,%1}, [%2];" : "=r"(a), "=r"(b) : "r"(addr));
}
__device__ __forceinline__ float4 lds128f(uint32_t addr) {
    float4 v;
    asm volatile("ld.shared.v4.f32 {%0,%1,%2,%3}, [%4];"
                 : "=f"(v.x), "=f"(v.y), "=f"(v.z), "=f"(v.w) : "r"(addr));
    return v;
}
__device__ __forceinline__ float silu_f(float x) {
    return x * (1.0f / (1.0f + __expf(-x)));
}
__device__ __forceinline__ uint32_t pack_h2(__half a, __half b) {
    __half2 t(a, b);
    return *reinterpret_cast<uint32_t*>(&t);
}
__device__ __forceinline__ uint32_t f2h2(float a, float b) {
    __half2 t = __floats2half2_rn(a, b);
    return *reinterpret_cast<uint32_t*>(&t);
}

// =================== Pass 1: silu -> fp16 (8 elems/thread) ===================
__global__ void __launch_bounds__(256)
silu_split_kernel(const float* __restrict__ q, const float* __restrict__ k)
{
    int j = blockIdx.x * 256 + threadIdx.x;   // 8-elem group index
    const float4* q4 = (const float4*)q + (size_t)j * 2;
    const float4* k4 = (const float4*)k + (size_t)j * 2;
    float4 a = q4[0], b = q4[1];
    uint4 o;
    o.x = pack_h2(__float2half(silu_f(a.x)), __float2half(silu_f(a.y)));
    o.y = pack_h2(__float2half(silu_f(a.z)), __float2half(silu_f(a.w)));
    o.z = pack_h2(__float2half(silu_f(b.x)), __float2half(silu_f(b.y)));
    o.w = pack_h2(__float2half(silu_f(b.z)), __float2half(silu_f(b.w)));
    ((uint4*)g_qh)[j] = o;
    a = k4[0]; b = k4[1];
    o.x = pack_h2(__float2half(silu_f(a.x)), __float2half(silu_f(a.y)));
    o.y = pack_h2(__float2half(silu_f(a.z)), __float2half(silu_f(a.w)));
    o.z = pack_h2(__float2half(silu_f(b.x)), __float2half(silu_f(b.y)));
    o.w = pack_h2(__float2half(silu_f(b.z)), __float2half(silu_f(b.w)));
    ((uint4*)g_kh)[j] = o;
}

// =================== Pass 2: persistent HMMA GEMM + fused softmax ===================
// 152 persistent CTAs x 512 threads (16 warp-private pipelines). Next item's
// Q + K prologue is interleaved into tiles 4..7 (uniform wait<3> ladder),
// Q double-buffered in smem. Single CTA barrier per item.
__global__ void __launch_bounds__(512, 1)
attn_mma_kernel(const float* __restrict__ scale_p, float* __restrict__ out)
{
    extern __shared__ char smem[];
    const uint32_t sb = smem_u32(smem);
    const int tid = threadIdx.x, lane = tid & 31, w = tid >> 5;
    const float sc = scale_p[0];

    const uint32_t myring = sb + OFF_K + (uint32_t)w * 8192;
    const uint32_t scb = sb + OFF_SC;
    float* rs = (float*)(smem + OFF_RS);    // [32 rows][16 warps]

    // Q chunk owned by this thread (row = tid>>4, c = tid&15)
    const int qrow = tid >> 4, qc = tid & 15;
    const uint32_t qchunk = (uint32_t)(qrow * 256 + (((qc ^ (qrow & 7)) & 15) << 4));

    auto pfQ = [&](int item, int buf) {
        int bh = item >> 5, mtile = item & 31;
        const char* src = (const char*)g_qh +
            (((size_t)(bh * Pp + mtile * BM) + qrow) * 256 + qc * 16);
        cpa16(sb + OFF_Q + (uint32_t)buf * 8192 + qchunk, src);
        cpa_commit();
    };
    auto pfK = [&](int item, int t) {
        int bh = item >> 5;
        uint32_t dst = myring + (uint32_t)(t & 3) * 2048;
        const char* src = (const char*)g_kh +
            ((size_t)(bh * Pp + t * TN + w * 8)) * 256;
        #pragma unroll
        for (int i = 0; i < 4; ++i) {
            int idx = lane + (i << 5);
            int key = idx >> 4, c = idx & 15;
            uint32_t off = (uint32_t)(key * 256) + (((c ^ (key & 7)) & 15) << 4);
            cpa16(dst + off, src + key * 256 + c * 16);
        }
        cpa_commit();
    };

    // fragment addressing constants
    const int lm = lane >> 3, lr = lane & 7;
    const int brow = lane & 7;
    const int bsel = (lane >> 3) & 3;     // ldsm.x4 fetches chunks of ks AND ks+1
    const uint32_t browoff = (uint32_t)brow * 256;
    const int r0 = lane >> 2;
    const uint32_t rx = (uint32_t)((r0 & 7) << 4);
    const uint32_t kcolbyte = (uint32_t)(w * 16 + 4 * (lane & 3));

    int item = blockIdx.x;
    int buf = 0;
    if (item < NITEMS) {
        pfQ(item, 0);
        #pragma unroll
        for (int t = 0; t < 4; ++t) pfK(item, t);
    }

    while (item < NITEMS) {
        const int next = item + NCTAS;
        const int pf = (next < NITEMS) ? next : 0;   // tail: harmless dummy prefetch
        const int nbuf = buf ^ 1;
        const int bh = item >> 5, mtile = item & 31;

        cpa_wait<4>();      // this item's Q complete (<=4 K groups may be pending)
        __syncthreads();    // Q visible CTA-wide; scores/rs free for reuse

        // ---- hoist Q fragments (2 row-groups x 8 ks) ----
        const uint32_t qbase = sb + OFF_Q + (uint32_t)buf * 8192;
        uint32_t aq[2][8][4];
        #pragma unroll
        for (int rg = 0; rg < 2; ++rg) {
            int arow = rg * 16 + ((lm & 1) << 3) + lr;
            uint32_t arow256 = (uint32_t)arow * 256;
            int ax7 = arow & 7, amc = lm >> 1;
            #pragma unroll
            for (int ks = 0; ks < 8; ++ks) {
                uint32_t ac = (uint32_t)((((2 * ks + amc) ^ ax7) & 15) << 4);
                ldsm4(aq[rg][ks], qbase + arow256 + ac);
            }
        }

        float s[4] = {0.f, 0.f, 0.f, 0.f};

        #pragma unroll
        for (int t = 0; t < NT; ++t) {
            // uniform ladder: exactly 3 groups newer than tile t's at this point
            cpa_wait<3>();

            const uint32_t Kb = myring + (uint32_t)(t & 3) * 2048;
            float acc0[4] = {0.f, 0.f, 0.f, 0.f};
            float acc1[4] = {0.f, 0.f, 0.f, 0.f};

            #pragma unroll
            for (int ks = 0; ks < 8; ks += 2) {
                uint32_t b4[4];   // mats {0,1}: ks lo/hi; {2,3}: ks+1 lo/hi
                uint32_t bc = (uint32_t)((((2 * ks + bsel) ^ brow) & 15) << 4);
                ldsm4(b4, Kb + browoff + bc);
                mma16816(acc0, aq[0][ks],     b4[0], b4[1]);
                mma16816(acc1, aq[1][ks],     b4[0], b4[1]);
                mma16816(acc0, aq[0][ks + 1], b4[2], b4[3]);
                mma16816(acc1, aq[1][ks + 1], b4[2], b4[3]);
            }

            // staged prefetch: in-item refills (t<4), then next item's prologue
            if (t < 4)       pfK(item, t + 4);   // slot t&3 just freed
            else if (t == 4) pfQ(pf, nbuf);
            else if (t == 5) pfK(pf, 0);         // slot 0 freed at t=4
            else if (t == 6) pfK(pf, 1);         // slot 1 freed at t=5
            else             pfK(pf, 2);         // slot 2 freed at t=6

            // exp + fp32 sums + fp16 pack + swizzled STS
            uint32_t kb = (uint32_t)t * 256 + kcolbyte;
            float e0, e1;
            e0 = __expf(sc * acc0[0]); e1 = __expf(sc * acc0[1]); s[0] += e0 + e1;
            sts32(scb + (uint32_t)r0 * 2048        + (kb ^ rx), f2h2(e0, e1));
            e0 = __expf(sc * acc0[2]); e1 = __expf(sc * acc0[3]); s[1] += e0 + e1;
            sts32(scb + (uint32_t)(r0 + 8) * 2048  + (kb ^ rx), f2h2(e0, e1));
            e0 = __expf(sc * acc1[0]); e1 = __expf(sc * acc1[1]); s[2] += e0 + e1;
            sts32(scb + (uint32_t)(r0 + 16) * 2048 + (kb ^ rx), f2h2(e0, e1));
            e0 = __expf(sc * acc1[2]); e1 = __expf(sc * acc1[3]); s[3] += e0 + e1;
            sts32(scb + (uint32_t)(r0 + 24) * 2048 + (kb ^ rx), f2h2(e0, e1));
        }
        pfK(pf, 3);   // slot 3 freed at t=7

        // ---- row sums: reduce over key-lanes, publish per-warp partials ----
        #pragma unroll
        for (int o = 1; o < 4; o <<= 1) {
            s[0] += __shfl_xor_sync(0xFFFFFFFFu, s[0], o);
            s[1] += __shfl_xor_sync(0xFFFFFFFFu, s[1], o);
            s[2] += __shfl_xor_sync(0xFFFFFFFFu, s[2], o);
            s[3] += __shfl_xor_sync(0xFFFFFFFFu, s[3], o);
        }
        if ((lane & 3) == 0) {
            rs[(r0)      * 16 + w] = s[0];
            rs[(r0 + 8)  * 16 + w] = s[1];
            rs[(r0 + 16) * 16 + w] = s[2];
            rs[(r0 + 24) * 16 + w] = s[3];
        }
        __syncthreads();   // publishes all score STS + rs (single barrier per item)

        // ---- coalesced normalize + store (per-thread inv: 4x LDS128 broadcast) ----
        const int row = tid >> 4, cc = tid & 15;
        float tot = 0.0f;
        #pragma unroll
        for (int i = 0; i < 4; ++i) {
            float4 v = lds128f(sb + OFF_RS + (uint32_t)(row * 64 + i * 16));
            tot += (v.x + v.y) + (v.z + v.w);
        }
        const float iv = 1.0f / tot;

        float* orow = out + ((size_t)bh * Pp + mtile * BM + row) * Pp;
        const uint32_t rbase = scb + (uint32_t)row * 2048;
        const uint32_t rxr = (uint32_t)((row & 7) << 4);
        #pragma unroll
        for (int p = 0; p < 16; ++p) {
            int key = cc * 4 + p * 64;
            uint32_t a, b;
            lds64(a, b, rbase + (((uint32_t)(key * 2)) ^ rxr));
            __half2 ha = *reinterpret_cast<__half2*>(&a);
            __half2 hb = *reinterpret_cast<__half2*>(&b);
            float2 fa = __half22float2(ha);
            float2 fb = __half22float2(hb);
            float4 v = make_float4(fa.x * iv, fa.y * iv, fb.x * iv, fb.y * iv);
            *(float4*)(orow + key) = v;
        }

        item = next;
        buf = nbuf;
    }
    cpa_wait<0>();   // drain tail dummy prefetches before exit
}

// =================== launch ===================
extern "C" void kernel_launch(void* const* d_in, const int* in_sizes, int n_in,
                              void* d_out, int out_size)
{
    const float* q     = (const float*)d_in[0];
    const float* k     = (const float*)d_in[1];
    const float* scale = (const float*)d_in[2];
    float* out = (float*)d_out;

    silu_split_kernel<<<NELEM / 8 / 256, 256>>>(q, k);

    cudaFuncSetAttribute(attn_mma_kernel,
                         cudaFuncAttributeMaxDynamicSharedMemorySize, SMEM2);
    attn_mma_kernel<<<NCTAS, 512, SMEM2>>>(scale, out);
}

// round 17
// speedup vs baseline: 1.0460x; 1.0244x over previous
#include <cuda_runtime.h>
#include <cuda_fp16.h>
#include <stdint.h>

constexpr int Bc = 4, Hc = 16, Pp = 1024, Dd = 128;
constexpr int NELEM = Bc * Hc * Pp * Dd;   // 8388608
constexpr int BM = 32;       // query rows per item
constexpr int TN = 128;      // keys per tile
constexpr int NT = Pp / TN;  // 8 tiles
constexpr int NITEMS = 2048; // 32 mtiles x 64 bh
constexpr int NCTAS = 152;   // GB300 SM count (1 CTA/SM, persistent)

// ---- device scratch: silu'd q, k as fp16 ----
__device__ __half g_qh[NELEM], g_kh[NELEM];

// ---- smem layout (bytes) ----
constexpr int OFF_Q   = 0;        // 2 bufs x 32 rows x 256B (swizzled) = 16384
constexpr int OFF_K   = 16384;    // 16 warps x 4 slots x 2KB = 131072
constexpr int OFF_SC  = 147456;   // 32 rows x 2048B fp16 scores = 65536
constexpr int OFF_RS  = 212992;   // 32 rows x 16 warps x 4B = 2048
constexpr int SMEM2   = 215040;

// =================== helpers ===================
__device__ __forceinline__ uint32_t smem_u32(const void* p) {
    uint32_t a;
    asm("{ .reg .u64 t; cvta.to.shared.u64 t, %1; cvt.u32.u64 %0, t; }" : "=r"(a) : "l"(p));
    return a;
}
__device__ __forceinline__ void cpa16(uint32_t dst, const void* src) {
    asm volatile("cp.async.cg.shared.global [%0], [%1], 16;" :: "r"(dst), "l"(src));
}
__device__ __forceinline__ void cpa_commit() { asm volatile("cp.async.commit_group;" ::: "memory"); }
template<int N>
__device__ __forceinline__ void cpa_wait() { asm volatile("cp.async.wait_group %0;" :: "n"(N) : "memory"); }

__device__ __forceinline__ void ldsm4(uint32_t* r, uint32_t addr) {
    asm volatile("ldmatrix.sync.aligned.m8n8.x4.shared.b16 {%0,%1,%2,%3}, [%4];"
                 : "=r"(r[0]), "=r"(r[1]), "=r"(r[2]), "=r"(r[3]) : "r"(addr));
}
__device__ __forceinline__ void mma16816(float* d, const uint32_t* a, uint32_t b0, uint32_t b1) {
    asm volatile(
        "mma.sync.aligned.m16n8k16.row.col.f32.f16.f16.f32 "
        "{%0,%1,%2,%3}, {%4,%5,%6,%7}, {%8,%9}, {%0,%1,%2,%3};"
        : "+f"(d[0]), "+f"(d[1]), "+f"(d[2]), "+f"(d[3])
        : "r"(a[0]), "r"(a[1]), "r"(a[2]), "r"(a[3]), "r"(b0), "r"(b1));
}
__device__ __forceinline__ void sts32(uint32_t addr, uint32_t v) {
    asm volatile("st.shared.u32 [%0], %1;" :: "r"(addr), "r"(v) : "memory");
}
__device__ __forceinline__ void lds64(uint32_t& a, uint32_t& b, uint32_t addr) {
    asm volatile("ld.shared.v2.u32 {%0,%1}, [%2];" : "=r"(a), "=r"(b) : "r"(addr));
}
__device__ __forceinline__ float4 lds128f(uint32_t addr) {
    float4 v;
    asm volatile("ld.shared.v4.f32 {%0,%1,%2,%3}, [%4];"
                 : "=f"(v.x), "=f"(v.y), "=f"(v.z), "=f"(v.w) : "r"(addr));
    return v;
}
__device__ __forceinline__ float silu_f(float x) {
    return x * (1.0f / (1.0f + __expf(-x)));
}
__device__ __forceinline__ uint32_t pack_h2(__half a, __half b) {
    __half2 t(a, b);
    return *reinterpret_cast<uint32_t*>(&t);
}
__device__ __forceinline__ uint32_t f2h2(float a, float b) {
    __half2 t = __floats2half2_rn(a, b);
    return *reinterpret_cast<uint32_t*>(&t);
}

// =================== Pass 1: silu -> fp16 (8 elems/thread) ===================
__global__ void __launch_bounds__(256)
silu_split_kernel(const float* __restrict__ q, const float* __restrict__ k)
{
    int j = blockIdx.x * 256 + threadIdx.x;   // 8-elem group index
    const float4* q4 = (const float4*)q + (size_t)j * 2;
    const float4* k4 = (const float4*)k + (size_t)j * 2;
    float4 a = q4[0], b = q4[1];
    uint4 o;
    o.x = pack_h2(__float2half(silu_f(a.x)), __float2half(silu_f(a.y)));
    o.y = pack_h2(__float2half(silu_f(a.z)), __float2half(silu_f(a.w)));
    o.z = pack_h2(__float2half(silu_f(b.x)), __float2half(silu_f(b.y)));
    o.w = pack_h2(__float2half(silu_f(b.z)), __float2half(silu_f(b.w)));
    ((uint4*)g_qh)[j] = o;
    a = k4[0]; b = k4[1];
    o.x = pack_h2(__float2half(silu_f(a.x)), __float2half(silu_f(a.y)));
    o.y = pack_h2(__float2half(silu_f(a.z)), __float2half(silu_f(a.w)));
    o.z = pack_h2(__float2half(silu_f(b.x)), __float2half(silu_f(b.y)));
    o.w = pack_h2(__float2half(silu_f(b.z)), __float2half(silu_f(b.w)));
    ((uint4*)g_kh)[j] = o;
}

// =================== Pass 2: persistent HMMA GEMM + fused softmax ===================
// 152 persistent CTAs x 512 threads (16 warp-private pipelines). K streamed in
// 2-tile cp.async groups (4 waits/item). Next item's Q + K prologue interleaved
// into tiles 5..7 + epilogue. Q double-buffered. Single CTA barrier per item.
__global__ void __launch_bounds__(512, 1)
attn_mma_kernel(const float* __restrict__ scale_p, float* __restrict__ out)
{
    extern __shared__ char smem[];
    const uint32_t sb = smem_u32(smem);
    const int tid = threadIdx.x, lane = tid & 31, w = tid >> 5;
    const float sc2 = scale_p[0] * 1.4426950408889634f;   // fold log2(e)

    const uint32_t myring = sb + OFF_K + (uint32_t)w * 8192;
    const uint32_t scb = sb + OFF_SC;

    // Q chunk owned by this thread (row = tid>>4, c = tid&15)
    const int qrow = tid >> 4, qc = tid & 15;
    const uint32_t qchunk = (uint32_t)(qrow * 256 + (((qc ^ (qrow & 7)) & 15) << 4));

    auto pfQ = [&](int item, int buf) {
        int bh = item >> 5, mtile = item & 31;
        const char* src = (const char*)g_qh +
            (((size_t)(bh * Pp + mtile * BM) + qrow) * 256 + qc * 16);
        cpa16(sb + OFF_Q + (uint32_t)buf * 8192 + qchunk, src);
        cpa_commit();
    };
    // 2-tile group: tiles {t, t+1} -> slots {t&3, (t+1)&3}
    auto pfK2 = [&](int item, int t) {
        int bh = item >> 5;
        #pragma unroll
        for (int th = 0; th < 2; ++th) {
            uint32_t dst = myring + (uint32_t)((t + th) & 3) * 2048;
            const char* src = (const char*)g_kh +
                ((size_t)(bh * Pp + (t + th) * TN + w * 8)) * 256;
            #pragma unroll
            for (int i = 0; i < 4; ++i) {
                int idx = lane + (i << 5);
                int key = idx >> 4, c = idx & 15;
                uint32_t off = (uint32_t)(key * 256) + (((c ^ (key & 7)) & 15) << 4);
                cpa16(dst + off, src + key * 256 + c * 16);
            }
        }
        cpa_commit();
    };

    // fragment addressing constants
    const int lm = lane >> 3, lr = lane & 7;
    const int brow = lane & 7;
    const int bsel = (lane >> 3) & 3;     // ldsm.x4 fetches chunks of ks AND ks+1
    const uint32_t browoff = (uint32_t)brow * 256;
    const int r0 = lane >> 2;
    const uint32_t rx = (uint32_t)((r0 & 7) << 4);
    const uint32_t kcolbyte = (uint32_t)(w * 16 + 4 * (lane & 3));

    int item = blockIdx.x;
    int buf = 0;
    if (item < NITEMS) {
        pfQ(item, 0);
        pfK2(item, 0);
        pfK2(item, 2);
    }

    while (item < NITEMS) {
        const int next = item + NCTAS;
        const int pf = (next < NITEMS) ? next : 0;   // tail: harmless dummy prefetch
        const int nbuf = buf ^ 1;
        const int bh = item >> 5, mtile = item & 31;

        cpa_wait<2>();      // this item's Q complete (2 K groups may be pending)
        __syncthreads();    // Q visible CTA-wide; scores/rs free for reuse

        // ---- hoist Q fragments (2 row-groups x 8 ks) ----
        const uint32_t qbase = sb + OFF_Q + (uint32_t)buf * 8192;
        uint32_t aq[2][8][4];
        #pragma unroll
        for (int rg = 0; rg < 2; ++rg) {
            int arow = rg * 16 + ((lm & 1) << 3) + lr;
            uint32_t arow256 = (uint32_t)arow * 256;
            int ax7 = arow & 7, amc = lm >> 1;
            #pragma unroll
            for (int ks = 0; ks < 8; ++ks) {
                uint32_t ac = (uint32_t)((((2 * ks + amc) ^ ax7) & 15) << 4);
                ldsm4(aq[rg][ks], qbase + arow256 + ac);
            }
        }

        float s[4] = {0.f, 0.f, 0.f, 0.f};

        #pragma unroll
        for (int t = 0; t < NT; ++t) {
            // 2-tile groups: wait only on even tiles (t=6 has Qn+KA' newer)
            if (t == 0 || t == 2 || t == 4) cpa_wait<1>();
            else if (t == 6) cpa_wait<2>();

            const uint32_t Kb = myring + (uint32_t)(t & 3) * 2048;
            float acc0[4] = {0.f, 0.f, 0.f, 0.f};
            float acc1[4] = {0.f, 0.f, 0.f, 0.f};

            #pragma unroll
            for (int ks = 0; ks < 8; ks += 2) {
                uint32_t b4[4];   // mats {0,1}: ks lo/hi; {2,3}: ks+1 lo/hi
                uint32_t bc = (uint32_t)((((2 * ks + bsel) ^ brow) & 15) << 4);
                ldsm4(b4, Kb + browoff + bc);
                mma16816(acc0, aq[0][ks],     b4[0], b4[1]);
                mma16816(acc1, aq[1][ks],     b4[0], b4[1]);
                mma16816(acc0, aq[0][ks + 1], b4[2], b4[3]);
                mma16816(acc1, aq[1][ks + 1], b4[2], b4[3]);
            }

            // staged prefetch (2-tile groups):
            if (t == 1)      pfK2(item, 4);          // slots 0,1 freed at t=1
            else if (t == 3) pfK2(item, 6);          // slots 2,3 freed at t=3
            else if (t == 5) { pfQ(pf, nbuf); pfK2(pf, 0); }  // slots 0,1 freed at t=5
            // (pfK2(pf,2) issued after the loop: slots 2,3 freed at t=7)

            // exp2 + fp32 sums + fp16 pack + swizzled STS
            uint32_t kb = (uint32_t)t * 256 + kcolbyte;
            float e0, e1;
            e0 = exp2f(sc2 * acc0[0]); e1 = exp2f(sc2 * acc0[1]); s[0] += e0 + e1;
            sts32(scb + (uint32_t)r0 * 2048        + (kb ^ rx), f2h2(e0, e1));
            e0 = exp2f(sc2 * acc0[2]); e1 = exp2f(sc2 * acc0[3]); s[1] += e0 + e1;
            sts32(scb + (uint32_t)(r0 + 8) * 2048  + (kb ^ rx), f2h2(e0, e1));
            e0 = exp2f(sc2 * acc1[0]); e1 = exp2f(sc2 * acc1[1]); s[2] += e0 + e1;
            sts32(scb + (uint32_t)(r0 + 16) * 2048 + (kb ^ rx), f2h2(e0, e1));
            e0 = exp2f(sc2 * acc1[2]); e1 = exp2f(sc2 * acc1[3]); s[3] += e0 + e1;
            sts32(scb + (uint32_t)(r0 + 24) * 2048 + (kb ^ rx), f2h2(e0, e1));
        }
        pfK2(pf, 2);   // slots 2,3 freed at t=7

        // ---- row sums: reduce over key-lanes, publish per-warp partials ----
        #pragma unroll
        for (int o = 1; o < 4; o <<= 1) {
            s[0] += __shfl_xor_sync(0xFFFFFFFFu, s[0], o);
            s[1] += __shfl_xor_sync(0xFFFFFFFFu, s[1], o);
            s[2] += __shfl_xor_sync(0xFFFFFFFFu, s[2], o);
            s[3] += __shfl_xor_sync(0xFFFFFFFFu, s[3], o);
        }
        float* rs = (float*)(smem + OFF_RS);
        if ((lane & 3) == 0) {
            rs[(r0)      * 16 + w] = s[0];
            rs[(r0 + 8)  * 16 + w] = s[1];
            rs[(r0 + 16) * 16 + w] = s[2];
            rs[(r0 + 24) * 16 + w] = s[3];
        }
        __syncthreads();   // publishes all score STS + rs (single barrier per item)

        // ---- coalesced normalize + store (per-thread inv: 4x LDS128 broadcast) ----
        const int row = tid >> 4, cc = tid & 15;
        float tot = 0.0f;
        #pragma unroll
        for (int i = 0; i < 4; ++i) {
            float4 v = lds128f(sb + OFF_RS + (uint32_t)(row * 64 + i * 16));
            tot += (v.x + v.y) + (v.z + v.w);
        }
        const float iv = 1.0f / tot;

        float* orow = out + ((size_t)bh * Pp + mtile * BM + row) * Pp;
        const uint32_t rbase = scb + (uint32_t)row * 2048;
        const uint32_t rxr = (uint32_t)((row & 7) << 4);
        #pragma unroll
        for (int p = 0; p < 16; ++p) {
            int key = cc * 4 + p * 64;
            uint32_t a, b;
            lds64(a, b, rbase + (((uint32_t)(key * 2)) ^ rxr));
            __half2 ha = *reinterpret_cast<__half2*>(&a);
            __half2 hb = *reinterpret_cast<__half2*>(&b);
            float2 fa = __half22float2(ha);
            float2 fb = __half22float2(hb);
            float4 v = make_float4(fa.x * iv, fa.y * iv, fb.x * iv, fb.y * iv);
            *(float4*)(orow + key) = v;
        }

        item = next;
        buf = nbuf;
    }
    cpa_wait<0>();   // drain tail dummy prefetches before exit
}

// =================== launch ===================
extern "C" void kernel_launch(void* const* d_in, const int* in_sizes, int n_in,
                              void* d_out, int out_size)
{
    const float* q     = (const float*)d_in[0];
    const float* k     = (const float*)d_in[1];
    const float* scale = (const float*)d_in[2];
    float* out = (float*)d_out;

    silu_split_kernel<<<NELEM / 8 / 256, 256>>>(q, k);

    cudaFuncSetAttribute(attn_mma_kernel,
                         cudaFuncAttributeMaxDynamicSharedMemorySize, SMEM2);
    attn_mma_kernel<<<NCTAS, 512, SMEM2>>>(scale, out);
}